// round 6
// baseline (speedup 1.0000x reference)
#include <cuda_runtime.h>
#include <cstdint>

#define THREADS 128
#define MTILE 128
#define NTILE 128
#define KTILE 32
#define STAGES 3
#define STAGE_BYTES 32768          // A 16KB + B 16KB
#define SMEM_BYTES (STAGES * STAGE_BYTES)

// 16 MB scratch for h^T [512][8192] (tf32-rounded, bias added)
static __device__ float g_hT[512u * 8192u];

// XOR swizzle: 16B chunk index (bits[6:4]) ^= row%8 (bits[9:7])
#define SWZ(o) ((o) ^ (((o) >> 3) & 0x70))

__device__ __forceinline__ uint32_t smem_u32(const void* p){
    uint32_t a;
    asm("{ .reg .u64 t; cvta.to.shared.u64 t, %1; cvt.u32.u64 %0, t; }" : "=r"(a) : "l"(p));
    return a;
}
__device__ __forceinline__ void cp_async16(uint32_t dst, const void* src){
    asm volatile("cp.async.cg.shared.global [%0], [%1], 16;" :: "r"(dst), "l"(src) : "memory");
}
__device__ __forceinline__ void cp_commit(){ asm volatile("cp.async.commit_group;" ::: "memory"); }
template<int N> __device__ __forceinline__ void cp_wait(){
    asm volatile("cp.async.wait_group %0;" :: "n"(N) : "memory");
}
__device__ __forceinline__ uint32_t cvt_tf32(uint32_t bits){
    uint32_t r;
    asm("cvt.rna.tf32.f32 %0, %1;" : "=r"(r) : "f"(__uint_as_float(bits)));
    return r;
}
__device__ __forceinline__ float tf32_rna_f(float x){
    uint32_t y; asm("cvt.rna.tf32.f32 %0, %1;" : "=r"(y) : "f"(x));
    return __uint_as_float(y);
}
__device__ __forceinline__ void ldsm4(uint32_t& r0, uint32_t& r1, uint32_t& r2, uint32_t& r3,
                                      uint32_t addr){
    asm volatile("ldmatrix.sync.aligned.m8n8.x4.shared.b16 {%0,%1,%2,%3}, [%4];"
                 : "=r"(r0), "=r"(r1), "=r"(r2), "=r"(r3) : "r"(addr));
}
__device__ __forceinline__ void mma_tf32(float* c, const uint32_t* a, const uint32_t* b){
    asm volatile(
        "mma.sync.aligned.m16n8k8.row.col.f32.tf32.tf32.f32 "
        "{%0,%1,%2,%3}, {%4,%5,%6,%7}, {%8,%9}, {%0,%1,%2,%3};"
        : "+f"(c[0]), "+f"(c[1]), "+f"(c[2]), "+f"(c[3])
        : "r"(a[0]), "r"(a[1]), "r"(a[2]), "r"(a[3]), "r"(b[0]), "r"(b[1]));
}

// D[m][n] = sum_k A[m][k]*B[n][k]  (fp32 K-major; A rna-rounded on fragments,
// B rounded iff CVT_B; GEMM2 consumes pre-rounded hT so CVT_B=false there).
template<bool EPI_BIAS_ROUND, bool CVT_B>
__global__ void __launch_bounds__(THREADS, 2)
gemm_tf32(const float* __restrict__ A, const float* __restrict__ B,
          const float* __restrict__ bias, float* __restrict__ C,
          int ldA, int ldB, int ldC, int kiters)
{
    extern __shared__ char smem[];
    const uint32_t sb = smem_u32(smem);
    const int tid  = threadIdx.x;
    const int wid  = tid >> 5;
    const int lane = tid & 31;
    const int warp_m = wid & 1;       // 2 M-groups of 64
    const int warp_n = wid >> 1;      // 2 N-groups of 64
    const long m0 = (long)blockIdx.y * MTILE;
    const long n0 = (long)blockIdx.x * NTILE;

    float acc[4][8][4];
    #pragma unroll
    for (int i = 0; i < 4; i++)
        #pragma unroll
        for (int j = 0; j < 8; j++)
            #pragma unroll
            for (int k = 0; k < 4; k++) acc[i][j][k] = 0.0f;

    // producer geometry: 128 threads -> 16 rows x 8 chunks; 16 chunks/thread/stage
    const int prow = tid >> 3;          // 0..15
    const int pc   = (tid & 7) * 16;    // 16B chunk within 128B row

    auto copy_chunk = [&](long k0, uint32_t base, int j){
        if (j < 8){
            const int row = prow + j * 16;                       // A: 128 rows
            cp_async16(base + SWZ(row * 128 + pc),
                       A + (m0 + row) * (long)ldA + k0 + (pc >> 2));
        } else {
            const int row = prow + (j - 8) * 16;                 // B: 128 rows
            cp_async16(base + 16384u + SWZ(row * 128 + pc),
                       B + (n0 + row) * (long)ldB + k0 + (pc >> 2));
        }
    };

    // ldmatrix per-lane geometry (validated layout)
    const int rA  = (lane & 7) + ((lane >> 3) & 1) * 8;
    const int cbA = ((lane >> 4) & 1) * 16;
    const int rB  = (lane & 7) + ((lane >> 4) & 1) * 8;
    const int cbB = ((lane >> 3) & 1) * 16;

    // compute one k-tile from stage s; interleave 16 cp.asyncs for the tile at
    // k0n into stage basen (4 per k-step) when do_copy.
    auto compute = [&](int s, long k0n, uint32_t basen, bool do_copy){
        const uint32_t baseA = sb + (uint32_t)s * STAGE_BYTES;
        const uint32_t baseB = baseA + 16384u;
        uint32_t a[2][16], b[2][16];

        #pragma unroll
        for (int mt = 0; mt < 4; mt++){
            const int row = warp_m * 64 + mt * 16 + rA;
            ldsm4(a[0][mt*4+0], a[0][mt*4+1], a[0][mt*4+2], a[0][mt*4+3],
                  baseA + SWZ(row * 128 + cbA));
        }
        #pragma unroll
        for (int p = 0; p < 4; p++){
            const int row = warp_n * 64 + p * 16 + rB;
            ldsm4(b[0][p*4+0], b[0][p*4+1], b[0][p*4+2], b[0][p*4+3],
                  baseB + SWZ(row * 128 + cbB));
        }

        #pragma unroll
        for (int ks = 0; ks < 4; ks++){
            const int cur = ks & 1;
            const int nxt = cur ^ 1;
            const int kcn = (ks + 1) * 32;

            if (CVT_B){
                #pragma unroll
                for (int j = 0; j < 16; j++) b[cur][j] = cvt_tf32(b[cur][j]);
            }

            #pragma unroll
            for (int mt = 0; mt < 4; mt++){
                if (ks < 3){
                    const int rowA = warp_m * 64 + mt * 16 + rA;
                    ldsm4(a[nxt][mt*4+0], a[nxt][mt*4+1], a[nxt][mt*4+2], a[nxt][mt*4+3],
                          baseA + SWZ(rowA * 128 + kcn + cbA));
                    const int rowB = warp_n * 64 + mt * 16 + rB;
                    ldsm4(b[nxt][mt*4+0], b[nxt][mt*4+1], b[nxt][mt*4+2], b[nxt][mt*4+3],
                          baseB + SWZ(rowB * 128 + kcn + cbB));
                }
                #pragma unroll
                for (int j = 0; j < 4; j++) a[cur][mt*4+j] = cvt_tf32(a[cur][mt*4+j]);
                #pragma unroll
                for (int nt = 0; nt < 8; nt++)
                    mma_tf32(acc[mt][nt], &a[cur][mt * 4],
                             &b[cur][(nt >> 1) * 4 + (nt & 1) * 2]);
            }

            if (do_copy){
                copy_chunk(k0n, basen, 4 * ks + 0);
                copy_chunk(k0n, basen, 4 * ks + 1);
                copy_chunk(k0n, basen, 4 * ks + 2);
                copy_chunk(k0n, basen, 4 * ks + 3);
            }
        }
    };

    // prologue: fill stages 0..1
    #pragma unroll
    for (int s = 0; s < 2; s++){
        for (int j = 0; j < 16; j++)
            copy_chunk((long)s * KTILE, sb + (uint32_t)s * STAGE_BYTES, j);
        cp_commit();
    }

    for (int i = 0; i < kiters; i++){
        cp_wait<1>();                 // stage i arrived
        __syncthreads();              // everyone done reading stage (i+2)%3 (iter i-1)
        const bool dc = (i + 2 < kiters);
        compute(i % 3, (long)(i + 2) * KTILE,
                sb + (uint32_t)((i + 2) % 3) * STAGE_BYTES, dc);
        cp_commit();
    }

    // epilogue
    const int gid = lane >> 2, tig = lane & 3;
    #pragma unroll
    for (int mt = 0; mt < 4; mt++){
        const long r0 = m0 + warp_m * 64 + mt * 16 + gid;
        const long r1 = r0 + 8;
        float bv0 = 0.0f, bv1 = 0.0f;
        if (EPI_BIAS_ROUND){ bv0 = __ldg(bias + r0); bv1 = __ldg(bias + r1); }
        #pragma unroll
        for (int nt = 0; nt < 8; nt++){
            const long col = n0 + warp_n * 64 + nt * 8 + 2 * tig;
            float2 v0, v1;
            if (EPI_BIAS_ROUND){
                v0 = make_float2(tf32_rna_f(acc[mt][nt][0] + bv0),
                                 tf32_rna_f(acc[mt][nt][1] + bv0));
                v1 = make_float2(tf32_rna_f(acc[mt][nt][2] + bv1),
                                 tf32_rna_f(acc[mt][nt][3] + bv1));
            } else {
                v0 = make_float2(acc[mt][nt][0], acc[mt][nt][1]);
                v1 = make_float2(acc[mt][nt][2], acc[mt][nt][3]);
            }
            *(float2*)(C + r0 * ldC + col) = v0;
            *(float2*)(C + r1 * ldC + col) = v1;
        }
    }
}

extern "C" void kernel_launch(void* const* d_in, const int* in_sizes, int n_in,
                              void* d_out, int out_size)
{
    const float* input = (const float*)d_in[0];   // [8192, 512]
    const float* adj   = (const float*)d_in[1];   // [8192, 8192]
    const float* W     = (const float*)d_in[2];   // [512, 512]
    const float* bias  = (const float*)d_in[3];   // [512]
    float* out = (float*)d_out;                   // [8192, 512]

    cudaFuncSetAttribute(gemm_tf32<true, true>,
                         cudaFuncAttributeMaxDynamicSharedMemorySize, SMEM_BYTES);
    cudaFuncSetAttribute(gemm_tf32<false, false>,
                         cudaFuncAttributeMaxDynamicSharedMemorySize, SMEM_BYTES);

    float* hT = nullptr;
    cudaGetSymbolAddress((void**)&hT, g_hT);

    // GEMM1: hT[o][n] = tf32_rna(sum_i W[o][i]*input[n][i] + b[o])  (M=512, N=8192, K=512)
    gemm_tf32<true, true><<<dim3(8192 / NTILE, 512 / MTILE), THREADS, SMEM_BYTES>>>(
        W, input, bias, hT, 512, 512, 8192, 512 / KTILE);

    // GEMM2: out[m][o] = sum_k adj[m][k]*hT[o][k]   (M=8192, N=512, K=8192; B pre-rounded)
    gemm_tf32<false, false><<<dim3(512 / NTILE, 8192 / MTILE), THREADS, SMEM_BYTES>>>(
        adj, hT, nullptr, out, 8192, 8192, 512, 8192 / KTILE);
}

// round 7
// speedup vs baseline: 1.0633x; 1.0633x over previous
#include <cuda_runtime.h>
#include <cstdint>

#define THREADS 256
#define MTILE 128            // per group
#define NTILE 128            // per group; CTA covers 128 x 256
#define KTILE 32
#define STAGES 3
#define GRP_STAGE 32768      // A 16KB + B 16KB per group stage
#define GRP_BYTES (STAGES * GRP_STAGE)      // 96 KB per group
#define SMEM_BYTES (2 * GRP_BYTES)          // 192 KB

// 16 MB scratch for h^T [512][8192] (tf32-rounded, bias added)
static __device__ float g_hT[512u * 8192u];

// XOR swizzle: 16B chunk index (bits[6:4]) ^= row%8 (bits[9:7])
#define SWZ(o) ((o) ^ (((o) >> 3) & 0x70))

__device__ __forceinline__ uint32_t smem_u32(const void* p){
    uint32_t a;
    asm("{ .reg .u64 t; cvta.to.shared.u64 t, %1; cvt.u32.u64 %0, t; }" : "=r"(a) : "l"(p));
    return a;
}
__device__ __forceinline__ void cp_async16(uint32_t dst, const void* src){
    asm volatile("cp.async.cg.shared.global [%0], [%1], 16;" :: "r"(dst), "l"(src) : "memory");
}
__device__ __forceinline__ void cp_commit(){ asm volatile("cp.async.commit_group;" ::: "memory"); }
template<int N> __device__ __forceinline__ void cp_wait(){
    asm volatile("cp.async.wait_group %0;" :: "n"(N) : "memory");
}
__device__ __forceinline__ void bar_grp(int id){
    asm volatile("bar.sync %0, 128;" :: "r"(id) : "memory");
}
__device__ __forceinline__ uint32_t cvt_tf32(uint32_t bits){
    uint32_t r;
    asm("cvt.rna.tf32.f32 %0, %1;" : "=r"(r) : "f"(__uint_as_float(bits)));
    return r;
}
__device__ __forceinline__ float tf32_rna_f(float x){
    uint32_t y; asm("cvt.rna.tf32.f32 %0, %1;" : "=r"(y) : "f"(x));
    return __uint_as_float(y);
}
__device__ __forceinline__ void ldsm4(uint32_t& r0, uint32_t& r1, uint32_t& r2, uint32_t& r3,
                                      uint32_t addr){
    asm volatile("ldmatrix.sync.aligned.m8n8.x4.shared.b16 {%0,%1,%2,%3}, [%4];"
                 : "=r"(r0), "=r"(r1), "=r"(r2), "=r"(r3) : "r"(addr));
}
__device__ __forceinline__ void mma_tf32(float* c, const uint32_t* a, const uint32_t* b){
    asm volatile(
        "mma.sync.aligned.m16n8k8.row.col.f32.tf32.tf32.f32 "
        "{%0,%1,%2,%3}, {%4,%5,%6,%7}, {%8,%9}, {%0,%1,%2,%3};"
        : "+f"(c[0]), "+f"(c[1]), "+f"(c[2]), "+f"(c[3])
        : "r"(a[0]), "r"(a[1]), "r"(a[2]), "r"(a[3]), "r"(b[0]), "r"(b[1]));
}

// CTA = two independent groups (warps 0-3 / 4-7). Group g computes the
// 128 x 128 half-tile at n0 = blockIdx.x*256 + g*128, with private SMEM
// stages and a private named barrier. D[m][n] = sum_k A[m][k]*B[n][k].
template<bool EPI_BIAS_ROUND, bool CVT_B>
__global__ void __launch_bounds__(THREADS, 1)
gemm_tf32(const float* __restrict__ A, const float* __restrict__ B,
          const float* __restrict__ bias, float* __restrict__ C,
          int ldA, int ldB, int ldC, int kiters)
{
    extern __shared__ char smem[];
    const int tid   = threadIdx.x;
    const int wid   = tid >> 5;
    const int lane  = tid & 31;
    const int group = wid >> 2;           // 0 or 1
    const int gwid  = wid & 3;            // warp within group
    const int gtid  = tid & 127;          // thread within group
    const int warp_m = gwid & 1;          // 2 M-groups of 64
    const int warp_n = gwid >> 1;         // 2 N-groups of 64
    const int barid  = 1 + group;
    const uint32_t gb = smem_u32(smem) + (uint32_t)group * GRP_BYTES;
    const long m0 = (long)blockIdx.y * MTILE;
    const long n0 = (long)blockIdx.x * 256 + (long)group * NTILE;

    float acc[4][8][4];
    #pragma unroll
    for (int i = 0; i < 4; i++)
        #pragma unroll
        for (int j = 0; j < 8; j++)
            #pragma unroll
            for (int k = 0; k < 4; k++) acc[i][j][k] = 0.0f;

    // producer geometry (per group): 128 threads -> 16 rows x 8 chunks
    const int prow = gtid >> 3;          // 0..15
    const int pc   = (gtid & 7) * 16;    // 16B chunk within 128B row

    auto copy_chunk = [&](long k0, uint32_t base, int j){
        if (j < 8){
            const int row = prow + j * 16;                       // A: 128 rows
            cp_async16(base + SWZ(row * 128 + pc),
                       A + (m0 + row) * (long)ldA + k0 + (pc >> 2));
        } else {
            const int row = prow + (j - 8) * 16;                 // B: 128 rows
            cp_async16(base + 16384u + SWZ(row * 128 + pc),
                       B + (n0 + row) * (long)ldB + k0 + (pc >> 2));
        }
    };

    // ldmatrix per-lane geometry (validated layout)
    const int rA  = (lane & 7) + ((lane >> 3) & 1) * 8;
    const int cbA = ((lane >> 4) & 1) * 16;
    const int rB  = (lane & 7) + ((lane >> 4) & 1) * 8;
    const int cbB = ((lane >> 3) & 1) * 16;

    auto compute = [&](int s, long k0n, uint32_t basen, bool do_copy){
        const uint32_t baseA = gb + (uint32_t)s * GRP_STAGE;
        const uint32_t baseB = baseA + 16384u;
        uint32_t a[2][16], b[2][16];

        #pragma unroll
        for (int mt = 0; mt < 4; mt++){
            const int row = warp_m * 64 + mt * 16 + rA;
            ldsm4(a[0][mt*4+0], a[0][mt*4+1], a[0][mt*4+2], a[0][mt*4+3],
                  baseA + SWZ(row * 128 + cbA));
        }
        #pragma unroll
        for (int p = 0; p < 4; p++){
            const int row = warp_n * 64 + p * 16 + rB;
            ldsm4(b[0][p*4+0], b[0][p*4+1], b[0][p*4+2], b[0][p*4+3],
                  baseB + SWZ(row * 128 + cbB));
        }

        #pragma unroll
        for (int ks = 0; ks < 4; ks++){
            const int cur = ks & 1;
            const int nxt = cur ^ 1;
            const int kcn = (ks + 1) * 32;

            if (CVT_B){
                #pragma unroll
                for (int j = 0; j < 16; j++) b[cur][j] = cvt_tf32(b[cur][j]);
            }

            #pragma unroll
            for (int mt = 0; mt < 4; mt++){
                if (ks < 3){
                    const int rowA = warp_m * 64 + mt * 16 + rA;
                    ldsm4(a[nxt][mt*4+0], a[nxt][mt*4+1], a[nxt][mt*4+2], a[nxt][mt*4+3],
                          baseA + SWZ(rowA * 128 + kcn + cbA));
                    const int rowB = warp_n * 64 + mt * 16 + rB;
                    ldsm4(b[nxt][mt*4+0], b[nxt][mt*4+1], b[nxt][mt*4+2], b[nxt][mt*4+3],
                          baseB + SWZ(rowB * 128 + kcn + cbB));
                }
                #pragma unroll
                for (int j = 0; j < 4; j++) a[cur][mt*4+j] = cvt_tf32(a[cur][mt*4+j]);
                #pragma unroll
                for (int nt = 0; nt < 8; nt++)
                    mma_tf32(acc[mt][nt], &a[cur][mt * 4],
                             &b[cur][(nt >> 1) * 4 + (nt & 1) * 2]);
            }

            if (do_copy){
                copy_chunk(k0n, basen, 4 * ks + 0);
                copy_chunk(k0n, basen, 4 * ks + 1);
                copy_chunk(k0n, basen, 4 * ks + 2);
                copy_chunk(k0n, basen, 4 * ks + 3);
            }
        }
    };

    // prologue: fill stages 0..1
    #pragma unroll
    for (int s = 0; s < 2; s++){
        for (int j = 0; j < 16; j++)
            copy_chunk((long)s * KTILE, gb + (uint32_t)s * GRP_STAGE, j);
        cp_commit();
    }

    for (int i = 0; i < kiters; i++){
        cp_wait<1>();                 // this thread's stage i copies arrived
        bar_grp(barid);               // group done reading stage (i+2)%3
        const bool dc = (i + 2 < kiters);
        compute(i % 3, (long)(i + 2) * KTILE,
                gb + (uint32_t)((i + 2) % 3) * GRP_STAGE, dc);
        cp_commit();
    }

    // epilogue
    const int gid = lane >> 2, tig = lane & 3;
    #pragma unroll
    for (int mt = 0; mt < 4; mt++){
        const long r0 = m0 + warp_m * 64 + mt * 16 + gid;
        const long r1 = r0 + 8;
        float bv0 = 0.0f, bv1 = 0.0f;
        if (EPI_BIAS_ROUND){ bv0 = __ldg(bias + r0); bv1 = __ldg(bias + r1); }
        #pragma unroll
        for (int nt = 0; nt < 8; nt++){
            const long col = n0 + warp_n * 64 + nt * 8 + 2 * tig;
            float2 v0, v1;
            if (EPI_BIAS_ROUND){
                v0 = make_float2(tf32_rna_f(acc[mt][nt][0] + bv0),
                                 tf32_rna_f(acc[mt][nt][1] + bv0));
                v1 = make_float2(tf32_rna_f(acc[mt][nt][2] + bv1),
                                 tf32_rna_f(acc[mt][nt][3] + bv1));
            } else {
                v0 = make_float2(acc[mt][nt][0], acc[mt][nt][1]);
                v1 = make_float2(acc[mt][nt][2], acc[mt][nt][3]);
            }
            *(float2*)(C + r0 * ldC + col) = v0;
            *(float2*)(C + r1 * ldC + col) = v1;
        }
    }
}

extern "C" void kernel_launch(void* const* d_in, const int* in_sizes, int n_in,
                              void* d_out, int out_size)
{
    const float* input = (const float*)d_in[0];   // [8192, 512]
    const float* adj   = (const float*)d_in[1];   // [8192, 8192]
    const float* W     = (const float*)d_in[2];   // [512, 512]
    const float* bias  = (const float*)d_in[3];   // [512]
    float* out = (float*)d_out;                   // [8192, 512]

    cudaFuncSetAttribute(gemm_tf32<true, true>,
                         cudaFuncAttributeMaxDynamicSharedMemorySize, SMEM_BYTES);
    cudaFuncSetAttribute(gemm_tf32<false, false>,
                         cudaFuncAttributeMaxDynamicSharedMemorySize, SMEM_BYTES);

    float* hT = nullptr;
    cudaGetSymbolAddress((void**)&hT, g_hT);

    // GEMM1: hT[o][n] = tf32_rna(sum_i W[o][i]*input[n][i] + b[o])  (M=512, N=8192, K=512)
    // CTA covers 128 x 256 -> grid (8192/256, 512/128) = (32, 4) = 128 CTAs
    gemm_tf32<true, true><<<dim3(8192 / 256, 512 / MTILE), THREADS, SMEM_BYTES>>>(
        W, input, bias, hT, 512, 512, 8192, 512 / KTILE);

    // GEMM2: out[m][o] = sum_k adj[m][k]*hT[o][k]   (M=8192, N=512, K=8192)
    // grid (512/256, 8192/128) = (2, 64) = 128 CTAs, one per SM, even wave
    gemm_tf32<false, false><<<dim3(512 / 256, 8192 / MTILE), THREADS, SMEM_BYTES>>>(
        adj, hT, nullptr, out, 8192, 8192, 512, 8192 / KTILE);
}

// round 8
// speedup vs baseline: 1.7001x; 1.5989x over previous
#include <cuda_runtime.h>
#include <cuda_fp16.h>
#include <cstdint>

// ---------------- scratch ----------------
static __device__ __half g_adj16[8192ull * 8192ull];   // 128 MB adj in fp16
static __device__ __half g_hT16[512u * 8192u];         // 8 MB  h^T in fp16 (bias added)

// XOR swizzle: 16B chunk index (bits[6:4]) ^= row%8 (bits[9:7])
#define SWZ(o) ((o) ^ (((o) >> 3) & 0x70))

__device__ __forceinline__ uint32_t smem_u32(const void* p){
    uint32_t a;
    asm("{ .reg .u64 t; cvta.to.shared.u64 t, %1; cvt.u32.u64 %0, t; }" : "=r"(a) : "l"(p));
    return a;
}
__device__ __forceinline__ void cp_async16(uint32_t dst, const void* src){
    asm volatile("cp.async.cg.shared.global [%0], [%1], 16;" :: "r"(dst), "l"(src) : "memory");
}
__device__ __forceinline__ void cp_commit(){ asm volatile("cp.async.commit_group;" ::: "memory"); }
template<int N> __device__ __forceinline__ void cp_wait(){
    asm volatile("cp.async.wait_group %0;" :: "n"(N) : "memory");
}
__device__ __forceinline__ uint32_t cvt_tf32(uint32_t bits){
    uint32_t r;
    asm("cvt.rna.tf32.f32 %0, %1;" : "=r"(r) : "f"(__uint_as_float(bits)));
    return r;
}
__device__ __forceinline__ void ldsm4(uint32_t& r0, uint32_t& r1, uint32_t& r2, uint32_t& r3,
                                      uint32_t addr){
    asm volatile("ldmatrix.sync.aligned.m8n8.x4.shared.b16 {%0,%1,%2,%3}, [%4];"
                 : "=r"(r0), "=r"(r1), "=r"(r2), "=r"(r3) : "r"(addr));
}
__device__ __forceinline__ void mma_tf32(float* c, const uint32_t* a, const uint32_t* b){
    asm volatile(
        "mma.sync.aligned.m16n8k8.row.col.f32.tf32.tf32.f32 "
        "{%0,%1,%2,%3}, {%4,%5,%6,%7}, {%8,%9}, {%0,%1,%2,%3};"
        : "+f"(c[0]), "+f"(c[1]), "+f"(c[2]), "+f"(c[3])
        : "r"(a[0]), "r"(a[1]), "r"(a[2]), "r"(a[3]), "r"(b[0]), "r"(b[1]));
}
__device__ __forceinline__ void mma_f16(float* c, const uint32_t* a, const uint32_t* b){
    asm volatile(
        "mma.sync.aligned.m16n8k16.row.col.f32.f16.f16.f32 "
        "{%0,%1,%2,%3}, {%4,%5,%6,%7}, {%8,%9}, {%0,%1,%2,%3};"
        : "+f"(c[0]), "+f"(c[1]), "+f"(c[2]), "+f"(c[3])
        : "r"(a[0]), "r"(a[1]), "r"(a[2]), "r"(a[3]), "r"(b[0]), "r"(b[1]));
}

// ================= convert: adj fp32 -> fp16 (rn) =================
__global__ void __launch_bounds__(256)
cvt_f32_to_f16(const float4* __restrict__ src, uint2* __restrict__ dst, int n4)
{
    int i = blockIdx.x * blockDim.x + threadIdx.x;
    const int stride = gridDim.x * blockDim.x;
    for (; i < n4; i += stride){
        const float4 v = src[i];
        const __half2 h0 = __floats2half2_rn(v.x, v.y);
        const __half2 h1 = __floats2half2_rn(v.z, v.w);
        uint2 o;
        o.x = *(const uint32_t*)&h0;
        o.y = *(const uint32_t*)&h1;
        dst[i] = o;
    }
}

// ================= GEMM1: tf32, fp16 output =================
// hT16[m][n] = half(sum_k A[m][k]*B[n][k] + bias[m]); A=W [512,512], B=input [8192,512]
#define G1_THREADS 256
#define G1_STAGE 49152
__global__ void __launch_bounds__(G1_THREADS, 1)
gemm1_tf32(const float* __restrict__ A, const float* __restrict__ B,
           const float* __restrict__ bias, __half* __restrict__ C,
           int ldA, int ldB, int ldC, int kiters)
{
    extern __shared__ char smem[];
    const uint32_t sb = smem_u32(smem);
    const int tid  = threadIdx.x;
    const int wid  = tid >> 5;
    const int lane = tid & 31;
    const int warp_m = wid & 1;
    const int warp_n = wid >> 1;
    const long m0 = (long)blockIdx.y * 128;
    const long n0 = (long)blockIdx.x * 256;

    float acc[4][8][4];
    #pragma unroll
    for (int i = 0; i < 4; i++)
        #pragma unroll
        for (int j = 0; j < 8; j++)
            #pragma unroll
            for (int k = 0; k < 4; k++) acc[i][j][k] = 0.0f;

    const int prow = tid >> 3;
    const int pc   = (tid & 7) * 16;

    auto copy_chunk = [&](long k0, uint32_t base, int j){
        if (j < 4){
            const int row = prow + j * 32;
            cp_async16(base + SWZ(row * 128 + pc),
                       A + (m0 + row) * (long)ldA + k0 + (pc >> 2));
        } else {
            const int row = prow + (j - 4) * 32;
            cp_async16(base + 16384u + SWZ(row * 128 + pc),
                       B + (n0 + row) * (long)ldB + k0 + (pc >> 2));
        }
    };

    const int rA  = (lane & 7) + ((lane >> 3) & 1) * 8;
    const int cbA = ((lane >> 4) & 1) * 16;
    const int rB  = (lane & 7) + ((lane >> 4) & 1) * 8;
    const int cbB = ((lane >> 3) & 1) * 16;

    auto compute = [&](int s, long k0n, uint32_t basen, bool do_copy){
        const uint32_t baseA = sb + (uint32_t)s * G1_STAGE;
        const uint32_t baseB = baseA + 16384u;
        uint32_t a[2][16], b[2][16];

        #pragma unroll
        for (int mt = 0; mt < 4; mt++){
            const int row = warp_m * 64 + mt * 16 + rA;
            ldsm4(a[0][mt*4+0], a[0][mt*4+1], a[0][mt*4+2], a[0][mt*4+3],
                  baseA + SWZ(row * 128 + cbA));
        }
        #pragma unroll
        for (int p = 0; p < 4; p++){
            const int row = warp_n * 64 + p * 16 + rB;
            ldsm4(b[0][p*4+0], b[0][p*4+1], b[0][p*4+2], b[0][p*4+3],
                  baseB + SWZ(row * 128 + cbB));
        }
        #pragma unroll
        for (int ks = 0; ks < 4; ks++){
            const int cur = ks & 1;
            const int nxt = cur ^ 1;
            const int kcn = (ks + 1) * 32;
            #pragma unroll
            for (int j = 0; j < 16; j++) b[cur][j] = cvt_tf32(b[cur][j]);
            #pragma unroll
            for (int mt = 0; mt < 4; mt++){
                if (ks < 3){
                    const int rowA = warp_m * 64 + mt * 16 + rA;
                    ldsm4(a[nxt][mt*4+0], a[nxt][mt*4+1], a[nxt][mt*4+2], a[nxt][mt*4+3],
                          baseA + SWZ(rowA * 128 + kcn + cbA));
                    const int rowB = warp_n * 64 + mt * 16 + rB;
                    ldsm4(b[nxt][mt*4+0], b[nxt][mt*4+1], b[nxt][mt*4+2], b[nxt][mt*4+3],
                          baseB + SWZ(rowB * 128 + kcn + cbB));
                }
                #pragma unroll
                for (int j = 0; j < 4; j++) a[cur][mt*4+j] = cvt_tf32(a[cur][mt*4+j]);
                #pragma unroll
                for (int nt = 0; nt < 8; nt++)
                    mma_tf32(acc[mt][nt], &a[cur][mt * 4],
                             &b[cur][(nt >> 1) * 4 + (nt & 1) * 2]);
            }
            if (do_copy){
                copy_chunk(k0n, basen, 3 * ks + 0);
                copy_chunk(k0n, basen, 3 * ks + 1);
                copy_chunk(k0n, basen, 3 * ks + 2);
            }
        }
    };

    #pragma unroll
    for (int s = 0; s < 3; s++){
        for (int j = 0; j < 12; j++)
            copy_chunk((long)s * 32, sb + (uint32_t)s * G1_STAGE, j);
        cp_commit();
    }
    for (int i = 0; i < kiters; i++){
        cp_wait<2>();
        __syncthreads();
        const bool dc = (i + 3 < kiters);
        compute(i & 3, (long)(i + 3) * 32,
                sb + (uint32_t)((i + 3) & 3) * G1_STAGE, dc);
        cp_commit();
    }

    const int gid = lane >> 2, tig = lane & 3;
    #pragma unroll
    for (int mt = 0; mt < 4; mt++){
        const long r0 = m0 + warp_m * 64 + mt * 16 + gid;
        const long r1 = r0 + 8;
        const float bv0 = __ldg(bias + r0);
        const float bv1 = __ldg(bias + r1);
        #pragma unroll
        for (int nt = 0; nt < 8; nt++){
            const long col = n0 + warp_n * 64 + nt * 8 + 2 * tig;
            const __half2 h0 = __floats2half2_rn(acc[mt][nt][0] + bv0, acc[mt][nt][1] + bv0);
            const __half2 h1 = __floats2half2_rn(acc[mt][nt][2] + bv1, acc[mt][nt][3] + bv1);
            *(__half2*)(C + r0 * ldC + col) = h0;
            *(__half2*)(C + r1 * ldC + col) = h1;
        }
    }
}

// ================= GEMM2: fp16 inputs, fp32 out =================
// out[m][n] = sum_k A16[m][k] * B16[n][k]; A16=adj fp16 [8192,8192], B16=hT16 [512,8192]
#define G2_THREADS 256
#define G2_KTILE 64          // fp16 elements: 128B rows
#define G2_STAGE 49152       // A 16KB + B 32KB
__global__ void __launch_bounds__(G2_THREADS, 1)
gemm2_f16(const __half* __restrict__ A, const __half* __restrict__ B,
          float* __restrict__ C, int ldA, int ldB, int ldC, int kiters)
{
    extern __shared__ char smem[];
    const uint32_t sb = smem_u32(smem);
    const int tid  = threadIdx.x;
    const int wid  = tid >> 5;
    const int lane = tid & 31;
    const int warp_m = wid & 1;       // 2 M-groups of 64
    const int warp_n = wid >> 1;      // 4 N-groups of 64
    const long m0 = (long)blockIdx.y * 128;
    const long n0 = (long)blockIdx.x * 256;

    float acc[4][8][4];
    #pragma unroll
    for (int i = 0; i < 4; i++)
        #pragma unroll
        for (int j = 0; j < 8; j++)
            #pragma unroll
            for (int k = 0; k < 4; k++) acc[i][j][k] = 0.0f;

    // producer: stage = A 128 rows x 128B + B 256 rows x 128B; 12 chunks/thread
    const int prow = tid >> 3;          // 0..31
    const int pc   = (tid & 7) * 16;    // byte chunk in 128B row

    auto copy_chunk = [&](long k0, uint32_t base, int j){
        if (j < 4){
            const int row = prow + j * 32;                       // A: 128 rows
            cp_async16(base + SWZ(row * 128 + pc),
                       A + (m0 + row) * (long)ldA + k0 + (pc >> 1));
        } else {
            const int row = prow + (j - 4) * 32;                 // B: 256 rows
            cp_async16(base + 16384u + SWZ(row * 128 + pc),
                       B + (n0 + row) * (long)ldB + k0 + (pc >> 1));
        }
    };

    // ldmatrix lane geometry (same formulas as validated tf32 path; on fp16
    // data they yield the m16n8k16 a0..a3 / {b0,b1} fragments directly)
    const int rA  = (lane & 7) + ((lane >> 3) & 1) * 8;
    const int cbA = ((lane >> 4) & 1) * 16;
    const int rB  = (lane & 7) + ((lane >> 4) & 1) * 8;
    const int cbB = ((lane >> 3) & 1) * 16;

    auto compute = [&](int s, long k0n, uint32_t basen, bool do_copy){
        const uint32_t baseA = sb + (uint32_t)s * G2_STAGE;
        const uint32_t baseB = baseA + 16384u;
        uint32_t a[2][16], b[2][16];

        // kstep 0 fragments (each kstep = 16 fp16 k = 32 bytes)
        #pragma unroll
        for (int mt = 0; mt < 4; mt++){
            const int row = warp_m * 64 + mt * 16 + rA;
            ldsm4(a[0][mt*4+0], a[0][mt*4+1], a[0][mt*4+2], a[0][mt*4+3],
                  baseA + SWZ(row * 128 + cbA));
        }
        #pragma unroll
        for (int p = 0; p < 4; p++){
            const int row = warp_n * 64 + p * 16 + rB;
            ldsm4(b[0][p*4+0], b[0][p*4+1], b[0][p*4+2], b[0][p*4+3],
                  baseB + SWZ(row * 128 + cbB));
        }

        #pragma unroll
        for (int ks = 0; ks < 4; ks++){
            const int cur = ks & 1;
            const int nxt = cur ^ 1;
            const int kcn = (ks + 1) * 32;
            #pragma unroll
            for (int mt = 0; mt < 4; mt++){
                if (ks < 3){
                    const int rowA = warp_m * 64 + mt * 16 + rA;
                    ldsm4(a[nxt][mt*4+0], a[nxt][mt*4+1], a[nxt][mt*4+2], a[nxt][mt*4+3],
                          baseA + SWZ(rowA * 128 + kcn + cbA));
                    const int rowB = warp_n * 64 + mt * 16 + rB;
                    ldsm4(b[nxt][mt*4+0], b[nxt][mt*4+1], b[nxt][mt*4+2], b[nxt][mt*4+3],
                          baseB + SWZ(rowB * 128 + kcn + cbB));
                }
                #pragma unroll
                for (int nt = 0; nt < 8; nt++)
                    mma_f16(acc[mt][nt], &a[cur][mt * 4],
                            &b[cur][(nt >> 1) * 4 + (nt & 1) * 2]);
            }
            if (do_copy){
                copy_chunk(k0n, basen, 3 * ks + 0);
                copy_chunk(k0n, basen, 3 * ks + 1);
                copy_chunk(k0n, basen, 3 * ks + 2);
            }
        }
    };

    // 4-stage pipeline (R4-validated control flow)
    #pragma unroll
    for (int s = 0; s < 3; s++){
        for (int j = 0; j < 12; j++)
            copy_chunk((long)s * G2_KTILE, sb + (uint32_t)s * G2_STAGE, j);
        cp_commit();
    }
    for (int i = 0; i < kiters; i++){
        cp_wait<2>();
        __syncthreads();
        const bool dc = (i + 3 < kiters);
        compute(i & 3, (long)(i + 3) * G2_KTILE,
                sb + (uint32_t)((i + 3) & 3) * G2_STAGE, dc);
        cp_commit();
    }

    // epilogue (fp32 out, no bias)
    const int gid = lane >> 2, tig = lane & 3;
    #pragma unroll
    for (int mt = 0; mt < 4; mt++){
        const long r0 = m0 + warp_m * 64 + mt * 16 + gid;
        const long r1 = r0 + 8;
        #pragma unroll
        for (int nt = 0; nt < 8; nt++){
            const long col = n0 + warp_n * 64 + nt * 8 + 2 * tig;
            *(float2*)(C + r0 * ldC + col) = make_float2(acc[mt][nt][0], acc[mt][nt][1]);
            *(float2*)(C + r1 * ldC + col) = make_float2(acc[mt][nt][2], acc[mt][nt][3]);
        }
    }
}

// ---------------- launch ----------------
extern "C" void kernel_launch(void* const* d_in, const int* in_sizes, int n_in,
                              void* d_out, int out_size)
{
    const float* input = (const float*)d_in[0];   // [8192, 512]
    const float* adj   = (const float*)d_in[1];   // [8192, 8192]
    const float* W     = (const float*)d_in[2];   // [512, 512]
    const float* bias  = (const float*)d_in[3];   // [512]
    float* out = (float*)d_out;                   // [8192, 512]

    __half* adj16 = nullptr; cudaGetSymbolAddress((void**)&adj16, g_adj16);
    __half* hT16  = nullptr; cudaGetSymbolAddress((void**)&hT16,  g_hT16);

    const int G1_SMEM = 4 * G1_STAGE;   // 196608
    const int G2_SMEM = 4 * G2_STAGE;   // 196608
    cudaFuncSetAttribute(gemm1_tf32, cudaFuncAttributeMaxDynamicSharedMemorySize, G1_SMEM);
    cudaFuncSetAttribute(gemm2_f16,  cudaFuncAttributeMaxDynamicSharedMemorySize, G2_SMEM);

    // 1) adj -> fp16 (rn)
    cvt_f32_to_f16<<<2048, 256>>>((const float4*)adj, (uint2*)adj16, 8192 * 8192 / 4);

    // 2) GEMM1 (tf32): hT16[o][n] = half(sum_i W[o][i]*input[n][i] + b[o])
    gemm1_tf32<<<dim3(8192 / 256, 512 / 128), G1_THREADS, G1_SMEM>>>(
        W, input, bias, hT16, 512, 512, 8192, 512 / 32);

    // 3) GEMM2 (fp16): out[m][o] = sum_k adj16[m][k]*hT16[o][k]
    gemm2_f16<<<dim3(512 / 256, 8192 / 128), G2_THREADS, G2_SMEM>>>(
        adj16, hT16, out, 8192, 8192, 512, 8192 / G2_KTILE);
}